// round 6
// baseline (speedup 1.0000x reference)
#include <cuda_runtime.h>
#include <cuda_bf16.h>
#include <math.h>

// Problem constants
#define TQ  1024
#define BQ  64
#define IQ  256
#define HQ  512
#define H4Q 2048
#define OQ  128
#define MQ  65536  // B*T

// ---------------------------------------------------------------------------
// Scratch (static __device__ arrays: allocation-free per harness rules)
// ---------------------------------------------------------------------------
__device__ __align__(256) float g_xg[(size_t)2 * MQ * H4Q];          // [dir][b*T+t][4H] (1 GiB)
__device__ __align__(256) float g_y [(size_t)MQ * 2 * HQ];           // [b][t][dir*H+j]  (256 MB)
__device__ __align__(256) float g_hT[2 * 2 * HQ * BQ];               // [parity][dir][j][b]
__device__ __align__(256) float g_c [2 * BQ * HQ];                   // [dir][b][j]
__device__ __align__(256) float g_wstage[(size_t)2 * 32 * HQ * 64];  // [dir][jt][k][c] (16 MB)
__device__ unsigned g_bar_count[4];
__device__ unsigned g_bar_epoch[4];

__device__ __forceinline__ float sigmf(float x) { return 1.0f / (1.0f + __expf(-x)); }

// ---------------------------------------------------------------------------
// Init: zero state + barriers, and gather W_hh into per-CTA contiguous stage:
//   g_wstage[dir][jt][k][c] = W_hh_dir[(c>>4)*H + jt*16 + (c&15)][k]
// Runs every launch (graph replays must be deterministic).
// ---------------------------------------------------------------------------
__global__ void init_kernel(const float* __restrict__ Whh_f,
                            const float* __restrict__ Whh_b) {
    int idx = blockIdx.x * blockDim.x + threadIdx.x;

    const int WS_TOTAL = 2 * 32 * HQ * 64;  // 4,194,304
    if (idx < WS_TOTAL) {
        int dir = idx >> 20;            // 32*512*64 = 1M per dir
        int rem = idx & ((1 << 20) - 1);
        int jt  = rem >> 15;            // 512*64 = 32768 per jt
        int r2  = rem & 32767;
        int k   = r2 >> 6;
        int c   = r2 & 63;
        int gr  = (c >> 4) * HQ + jt * 16 + (c & 15);
        const float* W = dir ? Whh_b : Whh_f;
        g_wstage[idx] = W[(size_t)gr * HQ + k];
    }
    if (idx < 2 * 2 * HQ * BQ) g_hT[idx] = 0.0f;
    if (idx < 2 * BQ * HQ)     g_c[idx]  = 0.0f;
    if (idx < 4) { g_bar_count[idx] = 0u; g_bar_epoch[idx] = 0u; }
}

// ---------------------------------------------------------------------------
// C[M][N] = A[M][K] * W[N][K]^T + bias1[N] (+ bias2[N])
// 128x128 tile, 256 threads, 8x8 microtile, k-chunk 16, register prefetch.
// ---------------------------------------------------------------------------
__global__ __launch_bounds__(256, 2) void gemm_abt_kernel(
    const float* __restrict__ A, const float* __restrict__ W,
    const float* __restrict__ bias1, const float* __restrict__ bias2,
    float* __restrict__ C, int M, int N, int K)
{
    __shared__ float As[16][132];
    __shared__ float Bs[16][132];

    const int tid = threadIdx.x;
    const int tx  = tid & 15;
    const int ty  = tid >> 4;
    const int n0  = blockIdx.x * 128;
    const int m0  = blockIdx.y * 128;

    const int lr = tid >> 1;
    const int lc = (tid & 1) << 3;

    const float* Arow = A + (size_t)(m0 + lr) * K + lc;
    const float* Wrow = W + (size_t)(n0 + lr) * K + lc;

    float acc[8][8];
#pragma unroll
    for (int i = 0; i < 8; i++)
#pragma unroll
        for (int j = 0; j < 8; j++) acc[i][j] = 0.0f;

    float4 pa0 = *(const float4*)(Arow);
    float4 pa1 = *(const float4*)(Arow + 4);
    float4 pb0 = *(const float4*)(Wrow);
    float4 pb1 = *(const float4*)(Wrow + 4);

    for (int k0 = 0; k0 < K; k0 += 16) {
        As[lc+0][lr]=pa0.x; As[lc+1][lr]=pa0.y; As[lc+2][lr]=pa0.z; As[lc+3][lr]=pa0.w;
        As[lc+4][lr]=pa1.x; As[lc+5][lr]=pa1.y; As[lc+6][lr]=pa1.z; As[lc+7][lr]=pa1.w;
        Bs[lc+0][lr]=pb0.x; Bs[lc+1][lr]=pb0.y; Bs[lc+2][lr]=pb0.z; Bs[lc+3][lr]=pb0.w;
        Bs[lc+4][lr]=pb1.x; Bs[lc+5][lr]=pb1.y; Bs[lc+6][lr]=pb1.z; Bs[lc+7][lr]=pb1.w;
        __syncthreads();

        if (k0 + 16 < K) {
            pa0 = *(const float4*)(Arow + k0 + 16);
            pa1 = *(const float4*)(Arow + k0 + 20);
            pb0 = *(const float4*)(Wrow + k0 + 16);
            pb1 = *(const float4*)(Wrow + k0 + 20);
        }

#pragma unroll
        for (int kk = 0; kk < 16; kk++) {
            float4 x0 = *(const float4*)&As[kk][ty * 8];
            float4 x1 = *(const float4*)&As[kk][ty * 8 + 4];
            float4 y0 = *(const float4*)&Bs[kk][tx * 8];
            float4 y1 = *(const float4*)&Bs[kk][tx * 8 + 4];
            float av[8] = {x0.x, x0.y, x0.z, x0.w, x1.x, x1.y, x1.z, x1.w};
            float bv[8] = {y0.x, y0.y, y0.z, y0.w, y1.x, y1.y, y1.z, y1.w};
#pragma unroll
            for (int i = 0; i < 8; i++)
#pragma unroll
                for (int j = 0; j < 8; j++)
                    acc[i][j] = fmaf(av[i], bv[j], acc[i][j]);
        }
        __syncthreads();
    }

    float bv[8];
#pragma unroll
    for (int j = 0; j < 8; j++) {
        int n = n0 + tx * 8 + j;
        float b = bias1 ? bias1[n] : 0.0f;
        if (bias2) b += bias2[n];
        bv[j] = b;
    }
#pragma unroll
    for (int i = 0; i < 8; i++) {
        float* crow = C + (size_t)(m0 + ty * 8 + i) * N + n0 + tx * 8;
#pragma unroll
        for (int j = 0; j < 8; j++) crow[j] = acc[i][j] + bv[j];
    }
}

// ---------------------------------------------------------------------------
// Persistent LSTM: ONE kernel runs all 1024 steps for both directions.
// 128 CTAs: blockIdx = (jt 0..31, bt 0..1, dir 0..1). All co-resident
// (128 < 148 SMs). CTA (jt,bt,dir) only depends on CTAs sharing (bt,dir),
// so each 32-CTA group has its own software barrier.
// Tile per CTA: gates[32 b][64 gate-cols]; thread tile 2b x 4c.
// h double-buffered by step parity, stored transposed [j][b].
// ---------------------------------------------------------------------------
__global__ __launch_bounds__(256, 1) void lstm_persistent_kernel()
{
    const int jt  = blockIdx.x;
    const int bt  = blockIdx.y;
    const int dir = blockIdx.z;
    const int grp = dir * 2 + bt;
    const int j0  = jt * 16;
    const int b0  = bt * 32;

    const int tid = threadIdx.x;
    const int tx  = tid & 15;   // col group: 4 cols at c0 = tx*4
    const int ty  = tid >> 4;   // row pair:  rows r0 = ty*2, r0+1

    __shared__ float h_s[64][36];   // [k_local][b_local], pitch 36 (conflict-free)
    __shared__ float w_s[64][68];   // [k_local][c], pitch 68 (16B-aligned rows)
    __shared__ float g_s[32][68];   // gates for the update phase

    const float* wstage = g_wstage + ((size_t)dir * 32 + jt) * (HQ * 64);
    const float* xgd    = g_xg + (size_t)dir * MQ * H4Q;
    float*       cb     = g_c + (size_t)dir * BQ * HQ;

    // staging maps
    const int wk  = (tid >> 4) * 4;   // 4 k-rows of W per thread
    const int wcg = (tid & 15) * 4;   // 4 cols
    const int hk  = tid >> 2;         // 1 k-row of h per thread
    const int hb  = (tid & 3) * 8;    // 8 b values (2 float4)

    // output map
    const int c0 = tx * 4;
    const int gr = (c0 >> 4) * HQ + j0 + (c0 & 15);  // 4 contiguous gate cols
    const int r0 = ty * 2;

    for (int s = 0; s < TQ; s++) {
        const int t = dir ? (TQ - 1 - s) : s;
        const float* hread  = g_hT + (size_t)((s & 1) * 2 + dir) * (HQ * BQ);
        float*       hwrite = g_hT + (size_t)(((s + 1) & 1) * 2 + dir) * (HQ * BQ);

        // init accumulators from xg (includes both biases)
        float4 a0 = *(const float4*)(xgd + (size_t)((b0 + r0)     * TQ + t) * H4Q + gr);
        float4 a1 = *(const float4*)(xgd + (size_t)((b0 + r0 + 1) * TQ + t) * H4Q + gr);
        float acc[2][4] = {{a0.x, a0.y, a0.z, a0.w}, {a1.x, a1.y, a1.z, a1.w}};

        // prefetch chunk 0
        float4 wp[4], hp0, hp1;
#pragma unroll
        for (int i = 0; i < 4; i++)
            wp[i] = *(const float4*)(wstage + (size_t)(wk + i) * 64 + wcg);
        hp0 = *(const float4*)(hread + (size_t)hk * BQ + b0 + hb);
        hp1 = *(const float4*)(hread + (size_t)hk * BQ + b0 + hb + 4);

        for (int ch = 0; ch < 8; ch++) {     // 8 k-chunks of 64 (K = 512)
            __syncthreads();                  // prior compute done reading smem
#pragma unroll
            for (int i = 0; i < 4; i++)
                *(float4*)&w_s[wk + i][wcg] = wp[i];
            *(float4*)&h_s[hk][hb]     = hp0;
            *(float4*)&h_s[hk][hb + 4] = hp1;
            __syncthreads();

            if (ch < 7) {                    // prefetch next chunk (L2-resident)
                int k1 = (ch + 1) * 64;
#pragma unroll
                for (int i = 0; i < 4; i++)
                    wp[i] = *(const float4*)(wstage + (size_t)(k1 + wk + i) * 64 + wcg);
                hp0 = *(const float4*)(hread + (size_t)(k1 + hk) * BQ + b0 + hb);
                hp1 = *(const float4*)(hread + (size_t)(k1 + hk) * BQ + b0 + hb + 4);
            }

#pragma unroll 8
            for (int k = 0; k < 64; k++) {
                float4 w = *(const float4*)&w_s[k][c0];   // LDS.128, 2 wavefronts
                float2 h = *(const float2*)&h_s[k][r0];   // LDS.64 broadcast, 1 wf
                acc[0][0] = fmaf(h.x, w.x, acc[0][0]);
                acc[0][1] = fmaf(h.x, w.y, acc[0][1]);
                acc[0][2] = fmaf(h.x, w.z, acc[0][2]);
                acc[0][3] = fmaf(h.x, w.w, acc[0][3]);
                acc[1][0] = fmaf(h.y, w.x, acc[1][0]);
                acc[1][1] = fmaf(h.y, w.y, acc[1][1]);
                acc[1][2] = fmaf(h.y, w.z, acc[1][2]);
                acc[1][3] = fmaf(h.y, w.w, acc[1][3]);
            }
        }

        // gates -> smem for CTA-local LSTM update
        __syncthreads();
        *(float4*)&g_s[r0][c0]     = make_float4(acc[0][0], acc[0][1], acc[0][2], acc[0][3]);
        *(float4*)&g_s[r0 + 1][c0] = make_float4(acc[1][0], acc[1][1], acc[1][2], acc[1][3]);
        __syncthreads();

        // LSTM update: 512 (b,j) pairs, 2 per thread. Gate order i,f,g,o.
#pragma unroll
        for (int u2 = 0; u2 < 2; u2++) {
            int u  = tid * 2 + u2;
            int bl = u >> 4;
            int jl = u & 15;
            float ig = sigmf(g_s[bl][jl]);
            float fg = sigmf(g_s[bl][16 + jl]);
            float gg = tanhf(g_s[bl][32 + jl]);
            float og = sigmf(g_s[bl][48 + jl]);
            int b = b0 + bl;
            int j = j0 + jl;
            float cp = cb[b * HQ + j];
            float cn = fmaf(fg, cp, ig * gg);
            float hn = og * tanhf(cn);
            cb[b * HQ + j] = cn;
            hwrite[(size_t)j * BQ + b] = hn;
            g_y[(size_t)(b * TQ + t) * (2 * HQ) + (size_t)dir * HQ + j] = hn;
        }

        // group barrier (skip after last step; kernel exit synchronizes)
        if (s + 1 < TQ) {
            __syncthreads();
            if (tid == 0) {
                __threadfence();
                unsigned prev = atomicAdd(&g_bar_count[grp], 1u);
                if (prev == 31u) {
                    g_bar_count[grp] = 0u;
                    __threadfence();
                    atomicExch(&g_bar_epoch[grp], (unsigned)(s + 1));
                } else {
                    while (atomicAdd(&g_bar_epoch[grp], 0u) < (unsigned)(s + 1))
                        __nanosleep(32);
                    __threadfence();
                }
            }
            __syncthreads();
        }
    }
}

// ---------------------------------------------------------------------------
// Final h/c into d_out tail. Final h lives in parity 0 ((1023+1)&1 == 0),
// transposed [j][b] -> emit [dir][b][j]. c is already [dir][b][j].
// ---------------------------------------------------------------------------
__global__ void final_copy_kernel(float* __restrict__ hn_out, float* __restrict__ cn_out) {
    int i = blockIdx.x * blockDim.x + threadIdx.x;
    if (i < 2 * BQ * HQ) {
        int dir = i / (BQ * HQ);
        int rem = i - dir * (BQ * HQ);
        int b = rem / HQ;
        int j = rem - b * HQ;
        hn_out[i] = g_hT[(size_t)dir * (HQ * BQ) + (size_t)j * BQ + b];
        cn_out[i] = g_c[i];
    }
}

// ---------------------------------------------------------------------------
extern "C" void kernel_launch(void* const* d_in, const int* in_sizes, int n_in,
                              void* d_out, int out_size) {
    const float* inputs = (const float*)d_in[0];
    const float* W_ih_f = (const float*)d_in[1];
    const float* W_hh_f = (const float*)d_in[2];
    const float* b_ih_f = (const float*)d_in[3];
    const float* b_hh_f = (const float*)d_in[4];
    const float* W_ih_b = (const float*)d_in[5];
    const float* W_hh_b = (const float*)d_in[6];
    const float* b_ih_b = (const float*)d_in[7];
    const float* b_hh_b = (const float*)d_in[8];
    const float* W_out  = (const float*)d_in[9];
    const float* b_out  = (const float*)d_in[10];
    float* out = (float*)d_out;

    float *p_xg = nullptr, *p_y = nullptr;
    cudaGetSymbolAddress((void**)&p_xg, g_xg);
    cudaGetSymbolAddress((void**)&p_y,  g_y);

    // Node 1: init (state zero + W gather + barrier reset)
    init_kernel<<<(2 * 32 * HQ * 64 + 255) / 256, 256>>>(W_hh_f, W_hh_b);

    // Nodes 2-3: xg[dir] = inputs * W_ih^T + (b_ih + b_hh)
    dim3 g1(H4Q / 128, MQ / 128);  // (16, 512)
    gemm_abt_kernel<<<g1, 256>>>(inputs, W_ih_f, b_ih_f, b_hh_f,
                                 p_xg, MQ, H4Q, IQ);
    gemm_abt_kernel<<<g1, 256>>>(inputs, W_ih_b, b_ih_b, b_hh_b,
                                 p_xg + (size_t)MQ * H4Q, MQ, H4Q, IQ);

    // Node 4: all 1024 recurrence steps in one persistent kernel
    dim3 gs(32, 2, 2);  // 128 CTAs, all co-resident
    lstm_persistent_kernel<<<gs, 256>>>();

    // Node 5: out = y * W_out^T + b_out
    dim3 g3(OQ / 128, MQ / 128);  // (1, 512)
    gemm_abt_kernel<<<g3, 256>>>(p_y, W_out, b_out, nullptr,
                                 out, MQ, OQ, 2 * HQ);

    // Node 6: h_n / c_n tail (only if the output buffer includes them)
    long long need = (long long)MQ * OQ + 4LL * BQ * HQ;
    if ((long long)out_size >= need)
        final_copy_kernel<<<(2 * BQ * HQ + 255) / 256, 256>>>(
            out + (size_t)MQ * OQ,
            out + (size_t)MQ * OQ + 2 * BQ * HQ);
}